// round 1
// baseline (speedup 1.0000x reference)
#include <cuda_runtime.h>
#include <math.h>

#define BB 8
#define NN 7168
#define UU 49152
#define CC 64
#define NTOK (BB*NN)        // 57344
#define NW1 8               // warps per block, kernel 1
#define NTILES (NTOK/16)    // 3584

__device__ float g_z[(size_t)NTOK * CC];

// ---------------------------------------------------------------------------
// Kernel 1: fused attention  ->  g_z[token][64]
//   per token (warp): q = x@Wq+bq; p_g = Wk_g @ q_g (scaled); s[t,g] = u_t . p_g;
//   softmax over t; w_g = sum_t attn*u_t; z = concat_g (w_g @ Wv)_gcols + bv
// smem (floats): Wq[4096] | WkT[64*68] | Wv[4096] | bq[64] | bv[64] | 8 x warp(1888)
// ---------------------------------------------------------------------------
__global__ __launch_bounds__(256, 2) void k_attn(
    const float* __restrict__ u, const float* __restrict__ x,
    const float* __restrict__ Wk, const float* __restrict__ Wq,
    const float* __restrict__ bq, const float* __restrict__ Wv,
    const float* __restrict__ bv)
{
    extern __shared__ float sm[];
    float* sWq  = sm;
    float* sWkT = sm + 4096;        // stride 68 (padded, [c][d])
    float* sWv  = sm + 8448;
    float* sbq  = sm + 12544;
    float* sbv  = sm + 12608;

    int tid = threadIdx.x;
    for (int idx = tid; idx < 4096; idx += 256) {
        sWq[idx] = Wq[idx];
        sWv[idx] = Wv[idx];
        int d = idx >> 6, c = idx & 63;
        sWkT[c * 68 + d] = Wk[idx];
    }
    if (tid < 64) { sbq[tid] = bq[tid]; sbv[tid] = bv[tid]; }
    __syncthreads();

    int w = tid >> 5, l = tid & 31;
    float* sw   = sm + 12672 + w * 1888;
    float* uts  = sw;               // [16][68]
    float* xrow = sw + 1088;        // [64]
    float* qs   = sw + 1152;        // [64]
    float* ps   = sw + 1216;        // [4][68]
    float* ss   = sw + 1488;        // [64]
    float* atn  = sw + 1552;        // [64]
    float* ws   = sw + 1616;        // [4][68]

    for (int tok = blockIdx.x * NW1 + w; tok < NTOK; tok += gridDim.x * NW1) {
        int b = tok / NN, n = tok - b * NN;
        int i, to, nb;
        if (n < 4096)      { i = 0; to = 4;  nb = 0;    }
        else if (n < 6144) { i = 1; to = 8;  nb = 4096; }
        else               { i = 2; to = 16; nb = 6144; }
        int nl = n - nb;
        int m  = nl * to;                               // row in concatenated u_i
        long base = (long)i * 8192 + m + ((m >= 8192) ? 16384 : 0);
        const float* up = u + ((long)b * UU + base) * CC;   // to*64 contiguous floats
        const float* xp = x + (long)tok * CC;

        if (l < 16) *(float4*)&xrow[l * 4] = ((const float4*)xp)[l];
        int nf4 = to * 16;
        for (int idx = l; idx < nf4; idx += 32) {
            float4 v = ((const float4*)up)[idx];
            int row = idx >> 4, c4 = (idx & 15) * 4;
            *(float4*)&uts[row * 68 + c4] = v;
        }
        __syncwarp();

        // q = x @ Wq + bq  (lane owns cols l, l+32)
        float q0 = sbq[l], q1 = sbq[l + 32];
        #pragma unroll 8
        for (int d = 0; d < 64; d++) {
            float xv = xrow[d];
            q0 += xv * sWq[d * 64 + l];
            q1 += xv * sWq[d * 64 + l + 32];
        }
        qs[l] = q0; qs[l + 32] = q1;
        __syncwarp();

        // p[g][d] = sum_c Wk[d][g*16+c] * q[g*16+c], scaled by 1/sqrt(64)
        float p0[4] = {0,0,0,0}, p1[4] = {0,0,0,0};
        #pragma unroll
        for (int g = 0; g < 4; g++) {
            #pragma unroll
            for (int c = 0; c < 16; c++) {
                float qv = qs[g * 16 + c];
                const float* wr = &sWkT[(g * 16 + c) * 68];
                p0[g] += wr[l] * qv;
                p1[g] += wr[l + 32] * qv;
            }
        }
        #pragma unroll
        for (int g = 0; g < 4; g++) {
            ps[g * 68 + l]      = p0[g] * 0.125f;
            ps[g * 68 + l + 32] = p1[g] * 0.125f;
        }
        __syncwarp();

        // scores: slot = (row, g), lane handles slot l (and l+32 when to=16)
        int slots = to * 4;
        if (l < slots) {
            int row = l >> 2, g = l & 3;
            float acc = 0.f;
            #pragma unroll 8
            for (int d = 0; d < 64; d++) acc += uts[row * 68 + d] * ps[g * 68 + d];
            ss[l] = acc;
        }
        if (slots > 32) {
            int s2 = l + 32, row = s2 >> 2, g = s2 & 3;
            float acc = 0.f;
            #pragma unroll 8
            for (int d = 0; d < 64; d++) acc += uts[row * 68 + d] * ps[g * 68 + d];
            ss[s2] = acc;
        }
        __syncwarp();

        // softmax over rows, one lane per group
        if (l < 4) {
            float mx = -1e30f;
            for (int r = 0; r < to; r++) mx = fmaxf(mx, ss[r * 4 + l]);
            float sum = 0.f;
            for (int r = 0; r < to; r++) {
                float e = expf(ss[r * 4 + l] - mx);
                atn[r * 4 + l] = e; sum += e;
            }
            float inv = 1.0f / sum;
            for (int r = 0; r < to; r++) atn[r * 4 + l] *= inv;
        }
        __syncwarp();

        // w[g][d] = sum_t attn[t][g] * u[t][d]   (lane owns d = l, l+32)
        float w0[4] = {0,0,0,0}, w1[4] = {0,0,0,0};
        for (int r = 0; r < to; r++) {
            float uv0 = uts[r * 68 + l], uv1 = uts[r * 68 + l + 32];
            float a0 = atn[r * 4 + 0], a1 = atn[r * 4 + 1];
            float a2 = atn[r * 4 + 2], a3 = atn[r * 4 + 3];
            w0[0] += a0 * uv0; w0[1] += a1 * uv0; w0[2] += a2 * uv0; w0[3] += a3 * uv0;
            w1[0] += a0 * uv1; w1[1] += a1 * uv1; w1[2] += a2 * uv1; w1[3] += a3 * uv1;
        }
        #pragma unroll
        for (int g = 0; g < 4; g++) {
            ws[g * 68 + l]      = w0[g];
            ws[g * 68 + l + 32] = w1[g];
        }
        __syncwarp();

        // z[c] = (w[g(c)] @ Wv[:,c]) + bv[c]
        int ga = l >> 4, gb = 2 + (l >> 4);
        float o0 = sbv[l], o1 = sbv[l + 32];
        #pragma unroll 8
        for (int d = 0; d < 64; d++) {
            o0 += ws[ga * 68 + d] * sWv[d * 64 + l];
            o1 += ws[gb * 68 + d] * sWv[d * 64 + l + 32];
        }
        g_z[(long)tok * 64 + l]      = o0;
        g_z[(long)tok * 64 + l + 32] = o1;
        __syncwarp();
    }
}

// ---------------------------------------------------------------------------
// Kernel 2: LN1 -> GELU MLP (64->256->64) -> LN2 + shortcut(x@Ws+bs) -> out
// 16-token tile per block-iteration; all weights smem-resident (~171 KB)
// ---------------------------------------------------------------------------
__global__ __launch_bounds__(512, 1) void k_mlp(
    const float* __restrict__ x,
    const float* __restrict__ g1, const float* __restrict__ be1,
    const float* __restrict__ Wm1, const float* __restrict__ bm1,
    const float* __restrict__ Wm2, const float* __restrict__ bm2,
    const float* __restrict__ g2, const float* __restrict__ be2,
    const float* __restrict__ Ws, const float* __restrict__ bs,
    float* __restrict__ out)
{
    extern __shared__ float sm[];
    float* sWm1 = sm;                // [64][256]
    float* sWm2 = sm + 16384;        // [256][64]
    float* sWs  = sm + 32768;        // [64][64]
    float* sbm1 = sm + 36864;
    float* sbm2 = sm + 37120;
    float* sbs  = sm + 37184;
    float* sg1  = sm + 37248;
    float* sbe1 = sm + 37312;
    float* sg2  = sm + 37376;
    float* sbe2 = sm + 37440;
    float* znS  = sm + 37504;        // [16][68]
    float* hS   = sm + 38592;        // [16][260]
    float* xS   = sm + 42752;        // [16][68]

    int tid = threadIdx.x;
    for (int idx = tid; idx < 16384; idx += 512) { sWm1[idx] = Wm1[idx]; sWm2[idx] = Wm2[idx]; }
    for (int idx = tid; idx < 4096; idx += 512) sWs[idx] = Ws[idx];
    if (tid < 256) sbm1[tid] = bm1[tid];
    if (tid < 64) {
        sbm2[tid] = bm2[tid]; sbs[tid] = bs[tid];
        sg1[tid] = g1[tid]; sbe1[tid] = be1[tid];
        sg2[tid] = g2[tid]; sbe2[tid] = be2[tid];
    }
    __syncthreads();

    int w = tid >> 5, l = tid & 31;
    int c2 = l * 2;

    for (int tile = blockIdx.x; tile < NTILES; tile += gridDim.x) {
        int tk0 = tile * 16;

        // (a) LN1 + stage x row; warp w owns token tk0+w
        {
            long tk = tk0 + w;
            float2 zv = *(const float2*)&g_z[tk * 64 + c2];
            float2 xv = *(const float2*)(x + tk * 64 + c2);
            *(float2*)&xS[w * 68 + c2] = xv;
            float s = zv.x + zv.y;
            #pragma unroll
            for (int o = 16; o; o >>= 1) s += __shfl_xor_sync(0xffffffffu, s, o);
            float mean = s * (1.0f / 64.0f);
            float d0 = zv.x - mean, d1 = zv.y - mean;
            float v = d0 * d0 + d1 * d1;
            #pragma unroll
            for (int o = 16; o; o >>= 1) v += __shfl_xor_sync(0xffffffffu, v, o);
            float rs = rsqrtf(v * (1.0f / 64.0f) + 1e-5f);
            znS[w * 68 + c2]     = d0 * rs * sg1[c2]     + sbe1[c2];
            znS[w * 68 + c2 + 1] = d1 * rs * sg1[c2 + 1] + sbe1[c2 + 1];
        }
        __syncthreads();

        // (b) h = gelu(zn @ Wm1 + bm1); thread: 2 cols x 4 tokens
        {
            int jj = (tid & 127) * 2;
            int t0 = (tid >> 7) * 4;
            float a[4][2];
            #pragma unroll
            for (int t = 0; t < 4; t++) { a[t][0] = sbm1[jj]; a[t][1] = sbm1[jj + 1]; }
            #pragma unroll 8
            for (int d = 0; d < 64; d++) {
                float2 wv = *(float2*)&sWm1[d * 256 + jj];
                #pragma unroll
                for (int t = 0; t < 4; t++) {
                    float zv = znS[(t0 + t) * 68 + d];
                    a[t][0] += zv * wv.x;
                    a[t][1] += zv * wv.y;
                }
            }
            #pragma unroll
            for (int t = 0; t < 4; t++) {
                float h0 = a[t][0], h1 = a[t][1];
                h0 = 0.5f * h0 * (1.0f + erff(h0 * 0.70710678118654752f));
                h1 = 0.5f * h1 * (1.0f + erff(h1 * 0.70710678118654752f));
                *(float2*)&hS[(t0 + t) * 260 + jj] = make_float2(h0, h1);
            }
        }
        __syncthreads();

        // (c)+(d) y = h @ Wm2 + bm2; LN2; + (x @ Ws + bs); warp per token
        {
            long tk = tk0 + w;
            float y0 = sbm2[c2], y1 = sbm2[c2 + 1];
            #pragma unroll 4
            for (int j = 0; j < 256; j += 2) {
                float2 hv = *(float2*)&hS[w * 260 + j];
                float2 wa = *(float2*)&sWm2[j * 64 + c2];
                float2 wb = *(float2*)&sWm2[(j + 1) * 64 + c2];
                y0 += hv.x * wa.x; y0 += hv.y * wb.x;
                y1 += hv.x * wa.y; y1 += hv.y * wb.y;
            }
            float s0 = sbs[c2], s1 = sbs[c2 + 1];
            #pragma unroll 8
            for (int d = 0; d < 64; d++) {
                float xv = xS[w * 68 + d];
                float2 wv = *(float2*)&sWs[d * 64 + c2];
                s0 += xv * wv.x; s1 += xv * wv.y;
            }
            float s = y0 + y1;
            #pragma unroll
            for (int o = 16; o; o >>= 1) s += __shfl_xor_sync(0xffffffffu, s, o);
            float mean = s * (1.0f / 64.0f);
            float d0 = y0 - mean, d1 = y1 - mean;
            float v = d0 * d0 + d1 * d1;
            #pragma unroll
            for (int o = 16; o; o >>= 1) v += __shfl_xor_sync(0xffffffffu, v, o);
            float rs = rsqrtf(v * (1.0f / 64.0f) + 1e-5f);
            float o0 = d0 * rs * sg2[c2]     + sbe2[c2]     + s0;
            float o1 = d1 * rs * sg2[c2 + 1] + sbe2[c2 + 1] + s1;
            *(float2*)(out + tk * 64 + c2) = make_float2(o0, o1);
        }
        __syncthreads();
    }
}

extern "C" void kernel_launch(void* const* d_in, const int* in_sizes, int n_in,
                              void* d_out, int out_size)
{
    const float* u   = (const float*)d_in[0];
    const float* x   = (const float*)d_in[1];
    const float* Wk  = (const float*)d_in[2];
    // d_in[3] = bk: softmax shift-invariant, exactly drops out
    const float* Wq  = (const float*)d_in[4];
    const float* bq  = (const float*)d_in[5];
    const float* Wv  = (const float*)d_in[6];
    const float* bv  = (const float*)d_in[7];
    const float* g1  = (const float*)d_in[8];
    const float* be1 = (const float*)d_in[9];
    const float* Wm1 = (const float*)d_in[10];
    const float* bm1 = (const float*)d_in[11];
    const float* Wm2 = (const float*)d_in[12];
    const float* bm2 = (const float*)d_in[13];
    const float* g2  = (const float*)d_in[14];
    const float* be2 = (const float*)d_in[15];
    const float* Ws  = (const float*)d_in[16];
    const float* bs  = (const float*)d_in[17];
    float* out = (float*)d_out;

    size_t sm1 = 27776 * sizeof(float);   // ~108.5 KB
    size_t sm2 = 43840 * sizeof(float);   // ~171.3 KB
    cudaFuncSetAttribute(k_attn, cudaFuncAttributeMaxDynamicSharedMemorySize, (int)sm1);
    cudaFuncSetAttribute(k_mlp,  cudaFuncAttributeMaxDynamicSharedMemorySize, (int)sm2);

    k_attn<<<888, 256, sm1>>>(u, x, Wk, Wq, bq, Wv, bv);
    k_mlp<<<148, 512, sm2>>>(x, g1, be1, Wm1, bm1, Wm2, bm2, g2, be2, Ws, bs, out);
}

// round 3
// speedup vs baseline: 1.0264x; 1.0264x over previous
#include <cuda_runtime.h>
#include <math.h>

#define BB 8
#define NN 7168
#define UU 49152
#define CC 64
#define NTOK (BB*NN)          // 57344
#define NW1 24                // warps per block, kernel 1
#define TILE2 32
#define NTILES2 (NTOK/TILE2)  // 1792

typedef unsigned long long u64;

__device__ float g_z[(size_t)NTOK * CC];

__device__ __forceinline__ u64 bc2(float x) {
    u64 r; asm("mov.b64 %0,{%1,%1};" : "=l"(r) : "f"(x)); return r;
}
__device__ __forceinline__ u64 ffma2(u64 a, u64 b, u64 c) {
    u64 d; asm("fma.rn.f32x2 %0,%1,%2,%3;" : "=l"(d) : "l"(a), "l"(b), "l"(c)); return d;
}
__device__ __forceinline__ u64 fmul2(u64 a, u64 b) {
    u64 d; asm("mul.rn.f32x2 %0,%1,%2;" : "=l"(d) : "l"(a), "l"(b)); return d;
}
__device__ __forceinline__ float2 up2(u64 v) {
    float2 f; asm("mov.b64 {%0,%1},%2;" : "=f"(f.x), "=f"(f.y) : "l"(v)); return f;
}
__device__ __forceinline__ float gelu1(float x) {
    return 0.5f * x * (1.0f + erff(x * 0.70710678118654752f));
}

// ---------------------------------------------------------------------------
// Kernel 1: fused attention -> g_z[token][64]   (warp per token, f32x2 math)
// smem: Wq[4096] | WkT[64*68] | Wv[4096] | bq[64] | bv[64] | 24 x scratch(1616)
// scratch: uts[16*68] xrow[64] qs[64] ss[64] atn[64] ps[4*68]
// ---------------------------------------------------------------------------
__global__ __launch_bounds__(768, 1) void k_attn(
    const float* __restrict__ u, const float* __restrict__ x,
    const float* __restrict__ Wk, const float* __restrict__ Wq,
    const float* __restrict__ bq, const float* __restrict__ Wv,
    const float* __restrict__ bv)
{
    extern __shared__ float sm[];
    float* sWq  = sm;               // [d][64]   0..4096
    float* sWkT = sm + 4096;        // [c][68]   4096..8448
    float* sWv  = sm + 8448;        // [d][64]   8448..12544
    float* sbq  = sm + 12544;       // 12544..12608
    float* sbv  = sm + 12608;       // 12608..12672

    int tid = threadIdx.x;
    for (int idx = tid; idx < 4096; idx += 768) {
        sWq[idx] = Wq[idx];
        sWv[idx] = Wv[idx];
        int d = idx >> 6, c = idx & 63;
        sWkT[c * 68 + d] = Wk[idx];
    }
    if (tid < 64) { sbq[tid] = bq[tid]; sbv[tid] = bv[tid]; }
    __syncthreads();

    int w = tid >> 5, l = tid & 31;
    float* sw   = sm + 12672 + w * 1616;
    float* uts  = sw;               // [16][68] (rows 0..3 reused for ws)
    float* xrow = sw + 1088;
    float* qs   = sw + 1152;
    float* ss   = sw + 1216;
    float* atn  = sw + 1280;
    float* ps   = sw + 1344;        // [4][68]
    int l2 = l * 2;

    for (int tok = blockIdx.x * NW1 + w; tok < NTOK; tok += gridDim.x * NW1) {
        int b = tok / NN, n = tok - b * NN;
        int i, to, nb;
        if (n < 4096)      { i = 0; to = 4;  nb = 0;    }
        else if (n < 6144) { i = 1; to = 8;  nb = 4096; }
        else               { i = 2; to = 16; nb = 6144; }
        int nl = n - nb;
        int m  = nl * to;
        long base = (long)i * 8192 + m + ((m >= 8192) ? 16384 : 0);
        const float* up = u + ((long)b * UU + base) * CC;
        const float* xp = x + (long)tok * CC;

        if (l < 16) *(float4*)&xrow[l * 4] = ((const float4*)xp)[l];
        int nf4 = to * 16;
        for (int idx = l; idx < nf4; idx += 32) {
            float4 v = ((const float4*)up)[idx];
            int row = idx >> 4, c4 = (idx & 15) * 4;
            *(float4*)&uts[row * 68 + c4] = v;
        }
        __syncwarp();

        // q = x @ Wq + bq  (lane owns col pair 2l,2l+1)
        {
            u64 qa = *(const u64*)&sbq[l2];
            #pragma unroll 8
            for (int d = 0; d < 64; d++)
                qa = ffma2(bc2(xrow[d]), *(const u64*)&sWq[d * 64 + l2], qa);
            *(u64*)&qs[l2] = qa;
        }
        __syncwarp();

        // p[g][d] = (Wk_g^T q_g) * scale  (lane owns d pair)
        {
            u64 pa[4] = {0, 0, 0, 0};
            #pragma unroll
            for (int g = 0; g < 4; g++) {
                #pragma unroll
                for (int c = 0; c < 16; c++) {
                    int cc = g * 16 + c;
                    pa[g] = ffma2(bc2(qs[cc]), *(const u64*)&sWkT[cc * 68 + l2], pa[g]);
                }
            }
            u64 sc = bc2(0.125f);
            #pragma unroll
            for (int g = 0; g < 4; g++)
                *(u64*)&ps[g * 68 + l2] = fmul2(pa[g], sc);
        }
        __syncwarp();

        // scores
        int slots = to * 4;
        if (l < slots) {
            int row = l >> 2, g = l & 3;
            u64 acc = 0;
            #pragma unroll 8
            for (int dp = 0; dp < 32; dp++)
                acc = ffma2(*(const u64*)&uts[row * 68 + dp * 2],
                            *(const u64*)&ps[g * 68 + dp * 2], acc);
            float2 f = up2(acc);
            ss[l] = f.x + f.y;
        }
        if (slots > 32) {
            int s2 = l + 32, row = s2 >> 2, g = s2 & 3;
            u64 acc = 0;
            #pragma unroll 8
            for (int dp = 0; dp < 32; dp++)
                acc = ffma2(*(const u64*)&uts[row * 68 + dp * 2],
                            *(const u64*)&ps[g * 68 + dp * 2], acc);
            float2 f = up2(acc);
            ss[s2] = f.x + f.y;
        }
        __syncwarp();

        // softmax over rows, one lane per group
        if (l < 4) {
            float mx = -1e30f;
            for (int r = 0; r < to; r++) mx = fmaxf(mx, ss[r * 4 + l]);
            float sum = 0.f;
            for (int r = 0; r < to; r++) {
                float e = expf(ss[r * 4 + l] - mx);
                atn[r * 4 + l] = e; sum += e;
            }
            float inv = 1.0f / sum;
            for (int r = 0; r < to; r++) atn[r * 4 + l] *= inv;
        }
        __syncwarp();

        // w[g][d] = sum_t attn[t][g] * u[t][d]  (lane owns d pair)
        {
            u64 wa[4] = {0, 0, 0, 0};
            for (int r = 0; r < to; r++) {
                u64 u2 = *(const u64*)&uts[r * 68 + l2];
                float4 a4 = *(const float4*)&atn[r * 4];
                wa[0] = ffma2(bc2(a4.x), u2, wa[0]);
                wa[1] = ffma2(bc2(a4.y), u2, wa[1]);
                wa[2] = ffma2(bc2(a4.z), u2, wa[2]);
                wa[3] = ffma2(bc2(a4.w), u2, wa[3]);
            }
            __syncwarp();          // all reads of uts done before overwrite
            #pragma unroll
            for (int g = 0; g < 4; g++)
                *(u64*)&uts[g * 68 + l2] = wa[g];   // ws lives in uts rows 0..3
        }
        __syncwarp();

        // z[c] = w[g(c)] . Wv[:,c] + bv[c]   (group of col 2l is (2l)>>4 = l>>3)
        {
            int g = l >> 3;
            u64 za = *(const u64*)&sbv[l2];
            #pragma unroll 8
            for (int d = 0; d < 64; d++)
                za = ffma2(bc2(uts[g * 68 + d]), *(const u64*)&sWv[d * 64 + l2], za);
            *(u64*)&g_z[(long)tok * 64 + l2] = za;
        }
        __syncwarp();
    }
}

// ---------------------------------------------------------------------------
// Kernel 2: LN1 -> GELU MLP -> LN2 + shortcut  (32-token tiles, 1024 thr)
// ---------------------------------------------------------------------------
__global__ __launch_bounds__(1024, 1) void k_mlp(
    const float* __restrict__ x,
    const float* __restrict__ g1, const float* __restrict__ be1,
    const float* __restrict__ Wm1, const float* __restrict__ bm1,
    const float* __restrict__ Wm2, const float* __restrict__ bm2,
    const float* __restrict__ g2, const float* __restrict__ be2,
    const float* __restrict__ Ws, const float* __restrict__ bs,
    float* __restrict__ out)
{
    extern __shared__ float sm[];
    float* sWm1 = sm;                // [64][256]
    float* sWm2 = sm + 16384;        // [256][64]
    float* sWs  = sm + 32768;        // [64][64]
    float* sbm1 = sm + 36864;
    float* sbm2 = sm + 37120;
    float* sbs  = sm + 37184;
    float* sg1  = sm + 37248;
    float* sbe1 = sm + 37312;
    float* sg2  = sm + 37376;
    float* sbe2 = sm + 37440;
    float* znS  = sm + 37504;        // [32][66]
    float* hS   = sm + 39616;        // [32][264]
    float* xS   = sm + 48064;        // [32][68]

    int tid = threadIdx.x;
    for (int idx = tid; idx < 16384; idx += 1024) { sWm1[idx] = Wm1[idx]; sWm2[idx] = Wm2[idx]; }
    for (int idx = tid; idx < 4096; idx += 1024) sWs[idx] = Ws[idx];
    if (tid < 256) sbm1[tid] = bm1[tid];
    if (tid < 64) {
        sbm2[tid] = bm2[tid]; sbs[tid] = bs[tid];
        sg1[tid] = g1[tid]; sbe1[tid] = be1[tid];
        sg2[tid] = g2[tid]; sbe2[tid] = be2[tid];
    }
    __syncthreads();

    int w = tid >> 5, l = tid & 31;
    int c2 = l * 2;
    int col4 = (tid & 63) * 4;
    int t0 = (tid >> 6) * 2;
    int t1 = t0 + 1;

    for (int tile = blockIdx.x; tile < NTILES2; tile += gridDim.x) {
        int tk0 = tile * TILE2;

        // (a) LN1 + stage x row; warp w owns token tk0+w
        {
            long tk = tk0 + w;
            float2 zv = *(const float2*)&g_z[tk * 64 + c2];
            float2 xv = *(const float2*)(x + tk * 64 + c2);
            *(float2*)&xS[w * 68 + c2] = xv;
            float s = zv.x + zv.y;
            #pragma unroll
            for (int o = 16; o; o >>= 1) s += __shfl_xor_sync(0xffffffffu, s, o);
            float mean = s * (1.0f / 64.0f);
            float d0 = zv.x - mean, d1 = zv.y - mean;
            float v = d0 * d0 + d1 * d1;
            #pragma unroll
            for (int o = 16; o; o >>= 1) v += __shfl_xor_sync(0xffffffffu, v, o);
            float rs = rsqrtf(v * (1.0f / 64.0f) + 1e-5f);
            znS[w * 66 + c2]     = d0 * rs * sg1[c2]     + sbe1[c2];
            znS[w * 66 + c2 + 1] = d1 * rs * sg1[c2 + 1] + sbe1[c2 + 1];
        }
        __syncthreads();

        // (b) h = gelu(zn @ Wm1 + bm1); thread: 4 cols x 2 tokens, f32x2
        {
            u64 blo = *(const u64*)&sbm1[col4];
            u64 bhi = *(const u64*)&sbm1[col4 + 2];
            u64 a00 = blo, a01 = bhi, a10 = blo, a11 = bhi;
            #pragma unroll 8
            for (int d = 0; d < 64; d++) {
                ulonglong2 wv = *(const ulonglong2*)&sWm1[d * 256 + col4];
                u64 z0 = bc2(znS[t0 * 66 + d]);
                u64 z1 = bc2(znS[t1 * 66 + d]);
                a00 = ffma2(z0, wv.x, a00);
                a01 = ffma2(z0, wv.y, a01);
                a10 = ffma2(z1, wv.x, a10);
                a11 = ffma2(z1, wv.y, a11);
            }
            float2 f00 = up2(a00), f01 = up2(a01), f10 = up2(a10), f11 = up2(a11);
            *(float4*)&hS[t0 * 264 + col4] =
                make_float4(gelu1(f00.x), gelu1(f00.y), gelu1(f01.x), gelu1(f01.y));
            *(float4*)&hS[t1 * 264 + col4] =
                make_float4(gelu1(f10.x), gelu1(f10.y), gelu1(f11.x), gelu1(f11.y));
        }
        __syncthreads();

        // (c) y = h @ Wm2 + bm2; LN2; + (x @ Ws + bs); warp per token
        {
            long tk = tk0 + w;
            u64 ya = *(const u64*)&sbm2[c2];
            #pragma unroll 8
            for (int j = 0; j < 256; j += 4) {
                float4 h4 = *(const float4*)&hS[w * 264 + j];
                ya = ffma2(bc2(h4.x), *(const u64*)&sWm2[(j + 0) * 64 + c2], ya);
                ya = ffma2(bc2(h4.y), *(const u64*)&sWm2[(j + 1) * 64 + c2], ya);
                ya = ffma2(bc2(h4.z), *(const u64*)&sWm2[(j + 2) * 64 + c2], ya);
                ya = ffma2(bc2(h4.w), *(const u64*)&sWm2[(j + 3) * 64 + c2], ya);
            }
            u64 sa = *(const u64*)&sbs[c2];
            #pragma unroll 8
            for (int d = 0; d < 64; d++)
                sa = ffma2(bc2(xS[w * 68 + d]), *(const u64*)&sWs[d * 64 + c2], sa);

            float2 y = up2(ya);
            float2 sc = up2(sa);
            float s = y.x + y.y;
            #pragma unroll
            for (int o = 16; o; o >>= 1) s += __shfl_xor_sync(0xffffffffu, s, o);
            float mean = s * (1.0f / 64.0f);
            float d0 = y.x - mean, d1 = y.y - mean;
            float v = d0 * d0 + d1 * d1;
            #pragma unroll
            for (int o = 16; o; o >>= 1) v += __shfl_xor_sync(0xffffffffu, v, o);
            float rs = rsqrtf(v * (1.0f / 64.0f) + 1e-5f);
            float o0 = d0 * rs * sg2[c2]     + sbe2[c2]     + sc.x;
            float o1 = d1 * rs * sg2[c2 + 1] + sbe2[c2 + 1] + sc.y;
            *(float2*)(out + tk * 64 + c2) = make_float2(o0, o1);
        }
        __syncthreads();
    }
}

extern "C" void kernel_launch(void* const* d_in, const int* in_sizes, int n_in,
                              void* d_out, int out_size)
{
    const float* u   = (const float*)d_in[0];
    const float* x   = (const float*)d_in[1];
    const float* Wk  = (const float*)d_in[2];
    // d_in[3] = bk: softmax shift-invariant, exactly drops out
    const float* Wq  = (const float*)d_in[4];
    const float* bq  = (const float*)d_in[5];
    const float* Wv  = (const float*)d_in[6];
    const float* bv  = (const float*)d_in[7];
    const float* g1  = (const float*)d_in[8];
    const float* be1 = (const float*)d_in[9];
    const float* Wm1 = (const float*)d_in[10];
    const float* bm1 = (const float*)d_in[11];
    const float* Wm2 = (const float*)d_in[12];
    const float* bm2 = (const float*)d_in[13];
    const float* g2  = (const float*)d_in[14];
    const float* be2 = (const float*)d_in[15];
    const float* Ws  = (const float*)d_in[16];
    const float* bs  = (const float*)d_in[17];
    float* out = (float*)d_out;

    size_t sm1 = (12672 + NW1 * 1616) * sizeof(float);   // ~206 KB
    size_t sm2 = 50240 * sizeof(float);                  // ~201 KB
    cudaFuncSetAttribute(k_attn, cudaFuncAttributeMaxDynamicSharedMemorySize, (int)sm1);
    cudaFuncSetAttribute(k_mlp,  cudaFuncAttributeMaxDynamicSharedMemorySize, (int)sm2);

    k_attn<<<148, 768, sm1>>>(u, x, Wk, Wq, bq, Wv, bv);
    k_mlp<<<148, 1024, sm2>>>(x, g1, be1, Wm1, bm1, Wm2, bm2, g2, be2, Ws, bs, out);
}

// round 4
// speedup vs baseline: 1.3758x; 1.3404x over previous
#include <cuda_runtime.h>
#include <math.h>

#define BB 8
#define NN 7168
#define UU 49152
#define CC 64
#define NTOK (BB*NN)          // 57344
#define NW1 24                // warps per block, kernel 1
#define TILE 112
#define NTILES (NTOK/TILE)    // 512

typedef unsigned long long u64;

__device__ float g_z[(size_t)NTOK * CC];

__device__ __forceinline__ u64 bc2(float x) {
    u64 r; asm("mov.b64 %0,{%1,%1};" : "=l"(r) : "f"(x)); return r;
}
__device__ __forceinline__ u64 ffma2(u64 a, u64 b, u64 c) {
    u64 d; asm("fma.rn.f32x2 %0,%1,%2,%3;" : "=l"(d) : "l"(a), "l"(b), "l"(c)); return d;
}
__device__ __forceinline__ u64 fmul2(u64 a, u64 b) {
    u64 d; asm("mul.rn.f32x2 %0,%1,%2;" : "=l"(d) : "l"(a), "l"(b)); return d;
}
__device__ __forceinline__ float2 up2(u64 v) {
    float2 f; asm("mov.b64 {%0,%1},%2;" : "=f"(f.x), "=f"(f.y) : "l"(v)); return f;
}
__device__ __forceinline__ float gelu1(float x) {
    return 0.5f * x * (1.0f + erff(x * 0.70710678118654752f));
}

// ---------------------------------------------------------------------------
// Kernel 1: fused attention -> g_z[token][64]   (warp per token, f32x2 math)
// (unchanged from R3 — passed at rel_err 2.9e-7)
// ---------------------------------------------------------------------------
__global__ __launch_bounds__(768, 1) void k_attn(
    const float* __restrict__ u, const float* __restrict__ x,
    const float* __restrict__ Wk, const float* __restrict__ Wq,
    const float* __restrict__ bq, const float* __restrict__ Wv,
    const float* __restrict__ bv)
{
    extern __shared__ float sm[];
    float* sWq  = sm;               // [d][64]
    float* sWkT = sm + 4096;        // [c][68]
    float* sWv  = sm + 8448;        // [d][64]
    float* sbq  = sm + 12544;
    float* sbv  = sm + 12608;

    int tid = threadIdx.x;
    for (int idx = tid; idx < 4096; idx += 768) {
        sWq[idx] = Wq[idx];
        sWv[idx] = Wv[idx];
        int d = idx >> 6, c = idx & 63;
        sWkT[c * 68 + d] = Wk[idx];
    }
    if (tid < 64) { sbq[tid] = bq[tid]; sbv[tid] = bv[tid]; }
    __syncthreads();

    int w = tid >> 5, l = tid & 31;
    float* sw   = sm + 12672 + w * 1616;
    float* uts  = sw;               // [16][68] (rows 0..3 reused for ws)
    float* xrow = sw + 1088;
    float* qs   = sw + 1152;
    float* ss   = sw + 1216;
    float* atn  = sw + 1280;
    float* ps   = sw + 1344;        // [4][68]
    int l2 = l * 2;

    for (int tok = blockIdx.x * NW1 + w; tok < NTOK; tok += gridDim.x * NW1) {
        int b = tok / NN, n = tok - b * NN;
        int i, to, nb;
        if (n < 4096)      { i = 0; to = 4;  nb = 0;    }
        else if (n < 6144) { i = 1; to = 8;  nb = 4096; }
        else               { i = 2; to = 16; nb = 6144; }
        int nl = n - nb;
        int m  = nl * to;
        long base = (long)i * 8192 + m + ((m >= 8192) ? 16384 : 0);
        const float* up = u + ((long)b * UU + base) * CC;
        const float* xp = x + (long)tok * CC;

        if (l < 16) *(float4*)&xrow[l * 4] = ((const float4*)xp)[l];
        int nf4 = to * 16;
        for (int idx = l; idx < nf4; idx += 32) {
            float4 v = ((const float4*)up)[idx];
            int row = idx >> 4, c4 = (idx & 15) * 4;
            *(float4*)&uts[row * 68 + c4] = v;
        }
        __syncwarp();

        {
            u64 qa = *(const u64*)&sbq[l2];
            #pragma unroll 8
            for (int d = 0; d < 64; d++)
                qa = ffma2(bc2(xrow[d]), *(const u64*)&sWq[d * 64 + l2], qa);
            *(u64*)&qs[l2] = qa;
        }
        __syncwarp();

        {
            u64 pa[4] = {0, 0, 0, 0};
            #pragma unroll
            for (int g = 0; g < 4; g++) {
                #pragma unroll
                for (int c = 0; c < 16; c++) {
                    int cc = g * 16 + c;
                    pa[g] = ffma2(bc2(qs[cc]), *(const u64*)&sWkT[cc * 68 + l2], pa[g]);
                }
            }
            u64 sc = bc2(0.125f);
            #pragma unroll
            for (int g = 0; g < 4; g++)
                *(u64*)&ps[g * 68 + l2] = fmul2(pa[g], sc);
        }
        __syncwarp();

        int slots = to * 4;
        if (l < slots) {
            int row = l >> 2, g = l & 3;
            u64 acc = 0;
            #pragma unroll 8
            for (int dp = 0; dp < 32; dp++)
                acc = ffma2(*(const u64*)&uts[row * 68 + dp * 2],
                            *(const u64*)&ps[g * 68 + dp * 2], acc);
            float2 f = up2(acc);
            ss[l] = f.x + f.y;
        }
        if (slots > 32) {
            int s2 = l + 32, row = s2 >> 2, g = s2 & 3;
            u64 acc = 0;
            #pragma unroll 8
            for (int dp = 0; dp < 32; dp++)
                acc = ffma2(*(const u64*)&uts[row * 68 + dp * 2],
                            *(const u64*)&ps[g * 68 + dp * 2], acc);
            float2 f = up2(acc);
            ss[s2] = f.x + f.y;
        }
        __syncwarp();

        if (l < 4) {
            float mx = -1e30f;
            for (int r = 0; r < to; r++) mx = fmaxf(mx, ss[r * 4 + l]);
            float sum = 0.f;
            for (int r = 0; r < to; r++) {
                float e = expf(ss[r * 4 + l] - mx);
                atn[r * 4 + l] = e; sum += e;
            }
            float inv = 1.0f / sum;
            for (int r = 0; r < to; r++) atn[r * 4 + l] *= inv;
        }
        __syncwarp();

        {
            u64 wa[4] = {0, 0, 0, 0};
            for (int r = 0; r < to; r++) {
                u64 u2 = *(const u64*)&uts[r * 68 + l2];
                float4 a4 = *(const float4*)&atn[r * 4];
                wa[0] = ffma2(bc2(a4.x), u2, wa[0]);
                wa[1] = ffma2(bc2(a4.y), u2, wa[1]);
                wa[2] = ffma2(bc2(a4.z), u2, wa[2]);
                wa[3] = ffma2(bc2(a4.w), u2, wa[3]);
            }
            __syncwarp();
            #pragma unroll
            for (int g = 0; g < 4; g++)
                *(u64*)&uts[g * 68 + l2] = wa[g];
        }
        __syncwarp();

        {
            int g = l >> 3;
            u64 za = *(const u64*)&sbv[l2];
            #pragma unroll 8
            for (int d = 0; d < 64; d++)
                za = ffma2(bc2(uts[g * 68 + d]), *(const u64*)&sWv[d * 64 + l2], za);
            *(u64*)&g_z[(long)tok * 64 + l2] = za;
        }
        __syncwarp();
    }
}

// ---------------------------------------------------------------------------
// Kernel 2: LN1 -> GELU MLP -> LN2 + shortcut
// 112-token tiles, 1024 threads, token-blocked register tiling.
// smem (floats): Wm1[16384] Wm2[16384] bm1[256] bm2[64] g1 be1 g2 be2 bs [320]
//   zS[112*64]=7168 | hS[112*128]=14336 (reused: yS[112*66]=7392 + xS[112*64]=7168)
// total 55136 floats = 220.5 KB
// ---------------------------------------------------------------------------
__global__ __launch_bounds__(1024, 1) void k_mlp(
    const float* __restrict__ x,
    const float* __restrict__ g1, const float* __restrict__ be1,
    const float* __restrict__ Wm1, const float* __restrict__ bm1,
    const float* __restrict__ Wm2, const float* __restrict__ bm2,
    const float* __restrict__ g2, const float* __restrict__ be2,
    const float* __restrict__ Ws, const float* __restrict__ bs,
    float* __restrict__ out)
{
    extern __shared__ float sm[];
    float* sWm1 = sm;                 // [64][256]
    float* sWm2 = sm + 16384;         // [256][64]
    float* sbm1 = sm + 32768;         // [256]
    float* sbm2 = sm + 33024;
    float* sg1  = sm + 33088;
    float* sbe1 = sm + 33152;
    float* sg2  = sm + 33216;
    float* sbe2 = sm + 33280;
    float* sbs  = sm + 33344;
    float* zS   = sm + 33408;         // [112][64]
    float* hS   = sm + 40576;         // [112][128]
    float* yS   = hS;                 // [112][66]   (after C1)
    float* xS   = hS + 7392;          // [112][64]   (after C1)

    int tid = threadIdx.x;
    for (int idx = tid; idx < 16384; idx += 1024) { sWm1[idx] = Wm1[idx]; sWm2[idx] = Wm2[idx]; }
    if (tid < 256) sbm1[tid] = bm1[tid];
    if (tid < 64) {
        sbm2[tid] = bm2[tid];
        sg1[tid] = g1[tid]; sbe1[tid] = be1[tid];
        sg2[tid] = g2[tid]; sbe2[tid] = be2[tid];
        sbs[tid] = bs[tid];
    }
    __syncthreads();

    int w  = tid >> 5, l = tid & 31;
    int cg = l;                 // column-group (lane)
    int tg = w;                 // token-group (warp)
    bool act = (tg < 28);
    int t0 = tg * 4;
    int l2 = l * 2;
    const u64* WsG = (const u64*)Ws;   // Ws row d = 32 u64

    for (int tile = blockIdx.x; tile < NTILES; tile += gridDim.x) {
        long tk0 = (long)tile * TILE;

        // ---- A: LN1 -> zS[112][64]  (warp w<28: tokens t0..t0+3)
        if (act) {
            #pragma unroll
            for (int r = 0; r < 4; r++) {
                int t = t0 + r;
                float2 zv = *(const float2*)&g_z[(tk0 + t) * 64 + l2];
                float s = zv.x + zv.y;
                #pragma unroll
                for (int o = 16; o; o >>= 1) s += __shfl_xor_sync(0xffffffffu, s, o);
                float mean = s * (1.0f / 64.0f);
                float d0 = zv.x - mean, d1 = zv.y - mean;
                float v = d0 * d0 + d1 * d1;
                #pragma unroll
                for (int o = 16; o; o >>= 1) v += __shfl_xor_sync(0xffffffffu, v, o);
                float rs = rsqrtf(v * (1.0f / 64.0f) + 1e-5f);
                *(float2*)&zS[t * 64 + l2] =
                    make_float2(d0 * rs * sg1[l2] + sbe1[l2],
                                d1 * rs * sg1[l2 + 1] + sbe1[l2 + 1]);
            }
        }
        __syncthreads();

        // y accumulators (persist across both j-halves)
        u64 yac[4];
        {
            u64 yb = *(const u64*)&sbm2[l2];
            #pragma unroll
            for (int r = 0; r < 4; r++) yac[r] = yb;
        }

        #pragma unroll
        for (int half = 0; half < 2; half++) {
            int jb = half * 128;

            // ---- B: h = gelu(zn @ Wm1[:, jb:jb+128]); thread: 4 cols x 4 tokens
            if (act) {
                int jc = jb + cg * 4;
                u64 b0 = *(const u64*)&sbm1[jc];
                u64 b1 = *(const u64*)&sbm1[jc + 2];
                u64 a0[4], a1[4];
                #pragma unroll
                for (int r = 0; r < 4; r++) { a0[r] = b0; a1[r] = b1; }
                #pragma unroll 8
                for (int d = 0; d < 64; d++) {
                    ulonglong2 wv = *(const ulonglong2*)&sWm1[d * 256 + jc];
                    #pragma unroll
                    for (int r = 0; r < 4; r++) {
                        u64 z = bc2(zS[(t0 + r) * 64 + d]);
                        a0[r] = ffma2(z, wv.x, a0[r]);
                        a1[r] = ffma2(z, wv.y, a1[r]);
                    }
                }
                #pragma unroll
                for (int r = 0; r < 4; r++) {
                    float2 f0 = up2(a0[r]), f1 = up2(a1[r]);
                    *(float4*)&hS[(t0 + r) * 128 + cg * 4] =
                        make_float4(gelu1(f0.x), gelu1(f0.y), gelu1(f1.x), gelu1(f1.y));
                }
            }
            __syncthreads();

            // ---- C: y += h @ Wm2[jb:jb+128, :]; thread: 2 cols x 4 tokens
            if (act) {
                #pragma unroll 4
                for (int jj = 0; jj < 128; jj++) {
                    u64 wv = *(const u64*)&sWm2[(jb + jj) * 64 + l2];
                    #pragma unroll
                    for (int r = 0; r < 4; r++)
                        yac[r] = ffma2(bc2(hS[(t0 + r) * 128 + jj]), wv, yac[r]);
                }
            }
            __syncthreads();   // hS reused (next half / yS,xS)
        }

        // ---- W: spill y to yS
        if (act) {
            #pragma unroll
            for (int r = 0; r < 4; r++)
                *(u64*)&yS[(t0 + r) * 66 + l2] = yac[r];
        }
        // ---- X: stage x tile into xS (all threads)
        {
            const float4* xg = (const float4*)(x + tk0 * 64);
            for (int idx = tid; idx < TILE * 16; idx += 1024)
                ((float4*)xS)[idx] = xg[idx];
        }
        __syncthreads();

        // ---- L: LN2 in place on yS (warp per token, 4 rounds)
        if (act) {
            #pragma unroll
            for (int r = 0; r < 4; r++) {
                int t = t0 + r;
                float2 y = up2(*(const u64*)&yS[t * 66 + l2]);
                float s = y.x + y.y;
                #pragma unroll
                for (int o = 16; o; o >>= 1) s += __shfl_xor_sync(0xffffffffu, s, o);
                float mean = s * (1.0f / 64.0f);
                float d0 = y.x - mean, d1 = y.y - mean;
                float v = d0 * d0 + d1 * d1;
                #pragma unroll
                for (int o = 16; o; o >>= 1) v += __shfl_xor_sync(0xffffffffu, v, o);
                float rs = rsqrtf(v * (1.0f / 64.0f) + 1e-5f);
                *(float2*)&yS[t * 66 + l2] =
                    make_float2(d0 * rs * sg2[l2] + sbe2[l2],
                                d1 * rs * sg2[l2 + 1] + sbe2[l2 + 1]);
            }
        }
        // yS[t][2l] written & read by same thread; xS synced above.

        // ---- E: shortcut s = x @ Ws + bs (Ws from global/L2), out = LN2(y)+s
        if (act) {
            u64 sac[4];
            u64 sb = *(const u64*)&sbs[l2];
            #pragma unroll
            for (int r = 0; r < 4; r++) sac[r] = sb;
            #pragma unroll 8
            for (int d = 0; d < 64; d++) {
                u64 wv = __ldg(&WsG[d * 32 + cg]);
                #pragma unroll
                for (int r = 0; r < 4; r++)
                    sac[r] = ffma2(bc2(xS[(t0 + r) * 64 + d]), wv, sac[r]);
            }
            #pragma unroll
            for (int r = 0; r < 4; r++) {
                int t = t0 + r;
                float2 s = up2(sac[r]);
                float2 ln = *(const float2*)&yS[t * 66 + l2];
                *(float2*)(out + (tk0 + t) * 64 + l2) =
                    make_float2(ln.x + s.x, ln.y + s.y);
            }
        }
        __syncthreads();   // zS/hS reuse next tile
    }
}

extern "C" void kernel_launch(void* const* d_in, const int* in_sizes, int n_in,
                              void* d_out, int out_size)
{
    const float* u   = (const float*)d_in[0];
    const float* x   = (const float*)d_in[1];
    const float* Wk  = (const float*)d_in[2];
    // d_in[3] = bk: softmax shift-invariant, exactly drops out
    const float* Wq  = (const float*)d_in[4];
    const float* bq  = (const float*)d_in[5];
    const float* Wv  = (const float*)d_in[6];
    const float* bv  = (const float*)d_in[7];
    const float* g1  = (const float*)d_in[8];
    const float* be1 = (const float*)d_in[9];
    const float* Wm1 = (const float*)d_in[10];
    const float* bm1 = (const float*)d_in[11];
    const float* Wm2 = (const float*)d_in[12];
    const float* bm2 = (const float*)d_in[13];
    const float* g2  = (const float*)d_in[14];
    const float* be2 = (const float*)d_in[15];
    const float* Ws  = (const float*)d_in[16];
    const float* bs  = (const float*)d_in[17];
    float* out = (float*)d_out;

    size_t sm1 = (12672 + NW1 * 1616) * sizeof(float);   // ~206 KB
    size_t sm2 = 55136 * sizeof(float);                  // ~220.5 KB
    cudaFuncSetAttribute(k_attn, cudaFuncAttributeMaxDynamicSharedMemorySize, (int)sm1);
    cudaFuncSetAttribute(k_mlp,  cudaFuncAttributeMaxDynamicSharedMemorySize, (int)sm2);

    k_attn<<<148, 768, sm1>>>(u, x, Wk, Wq, bq, Wv, bv);
    k_mlp<<<148, 1024, sm2>>>(x, g1, be1, Wm1, bm1, Wm2, bm2, g2, be2, Ws, bs, out);
}